// round 13
// baseline (speedup 1.0000x reference)
#include <cuda_runtime.h>
#include <cuda_fp16.h>
#include <cstdint>

#define B_ 4
#define S_ 2048
#define D_ 1024
#define H_ 16
#define HD_ 64
#define OUT_ 256
#define M_ (B_*S_)
#define BH_ (B_*H_)

static constexpr size_t SZX = (size_t)M_ * D_;
static constexpr size_t SZW = (size_t)D_ * D_;
static constexpr size_t SZF = (size_t)D_ * OUT_;

static constexpr size_t O_X   = 0;                      // [Xq,Xk,Xv] hi, stride SZX
static constexpr size_t O_W   = O_X + 3 * SZX;          // [Wq,Wk,Wv]^T, stride SZW
static constexpr size_t O_WF  = O_W + 3 * SZW;
static constexpr size_t O_QH  = O_WF + SZF;
static constexpr size_t O_KH  = O_QH + SZX;
static constexpr size_t O_VH  = O_KH + SZX;
static constexpr size_t O_CH  = O_VH + SZX;
static constexpr size_t TOTAL_HF = O_CH + SZX;

__device__ __half g_hf[TOTAL_HF];

// ---------------- helpers ----------------
__device__ __forceinline__ uint32_t smem_u32(const void* p) {
    uint32_t a;
    asm("{ .reg .u64 t; cvta.to.shared.u64 t, %1; cvt.u32.u64 %0, t; }" : "=r"(a) : "l"(p));
    return a;
}
__device__ __forceinline__ void ldsm4(uint32_t* r, uint32_t a) {
    asm volatile("ldmatrix.sync.aligned.m8n8.x4.shared.b16 {%0,%1,%2,%3}, [%4];"
        : "=r"(r[0]), "=r"(r[1]), "=r"(r[2]), "=r"(r[3]) : "r"(a));
}
__device__ __forceinline__ void ldsm4t(uint32_t* r, uint32_t a) {
    asm volatile("ldmatrix.sync.aligned.m8n8.x4.trans.shared.b16 {%0,%1,%2,%3}, [%4];"
        : "=r"(r[0]), "=r"(r[1]), "=r"(r[2]), "=r"(r[3]) : "r"(a));
}
__device__ __forceinline__ void mma_f16(float* d, const uint32_t* a, const uint32_t* b) {
    asm volatile("mma.sync.aligned.m16n8k16.row.col.f32.f16.f16.f32 "
        "{%0,%1,%2,%3}, {%4,%5,%6,%7}, {%8,%9}, {%0,%1,%2,%3};"
        : "+f"(d[0]), "+f"(d[1]), "+f"(d[2]), "+f"(d[3])
        : "r"(a[0]), "r"(a[1]), "r"(a[2]), "r"(a[3]), "r"(b[0]), "r"(b[1]));
}
__device__ __forceinline__ void cpa16(uint32_t dst, const void* src) {
    asm volatile("cp.async.cg.shared.global [%0], [%1], 16;" :: "r"(dst), "l"(src));
}
#define CP_COMMIT() asm volatile("cp.async.commit_group;" ::: "memory")
#define CP_WAIT(n)  asm volatile("cp.async.wait_group %0;" :: "n"(n) : "memory")

__device__ __forceinline__ uint32_t swz128(uint32_t o) { return o ^ ((o >> 3) & 0x70); }
__device__ __forceinline__ uint32_t pack2h(float a, float b) {
    __half2 t = __floats2half2_rn(a, b);
    return *(uint32_t*)&t;
}
__device__ __forceinline__ float ex2f(float x) {
    float r;
    asm("ex2.approx.f32 %0, %1;" : "=f"(r) : "f"(x));
    return r;
}

// ---------------- conversions ----------------
__global__ void cvt3_h(const float* __restrict__ q, const float* __restrict__ k,
                       const float* __restrict__ v, __half* __restrict__ G, int n4) {
    const int z = blockIdx.y;
    const float* x = (z == 0) ? q : (z == 1) ? k : v;
    __half* hi = G + O_X + (size_t)z * SZX;
    int i = blockIdx.x * blockDim.x + threadIdx.x;
    if (i >= n4) return;
    float4 vv = ((const float4*)x)[i];
    ((uint32_t*)hi)[i*2]   = pack2h(vv.x, vv.y);
    ((uint32_t*)hi)[i*2+1] = pack2h(vv.z, vv.w);
}

// W [K][N] -> W^T [N][K] fp16; z=0..2: Wq/Wk/Wv (N=1024), z=3: Wf (N=256)
__global__ void transpose4_h(const float* __restrict__ Wq, const float* __restrict__ Wk,
                             const float* __restrict__ Wv, const float* __restrict__ Wf,
                             __half* __restrict__ G) {
    __shared__ float t[32][33];
    const int z = blockIdx.z;
    const float* W = (z == 0) ? Wq : (z == 1) ? Wk : (z == 2) ? Wv : Wf;
    __half* Th = (z < 3) ? (G + O_W + (size_t)z * SZW) : (G + O_WF);
    const int Ndim = (z < 3) ? D_ : OUT_;
    const int n0 = blockIdx.x * 32, k0 = blockIdx.y * 32;
    if (n0 >= Ndim) return;
    const int tx = threadIdx.x & 31, ty = threadIdx.x >> 5;
#pragma unroll
    for (int i = 0; i < 32; i += 8)
        t[ty + i][tx] = W[(size_t)(k0 + ty + i) * Ndim + n0 + tx];
    __syncthreads();
#pragma unroll
    for (int i = 0; i < 32; i += 8)
        Th[(size_t)(n0 + ty + i) * D_ + k0 + tx] = __float2half_rn(t[tx][ty + i]);
}

// ---------------- GEMM mainloop: acc += A[128,1024] @ B[128 rows,1024]^T -----
__device__ __forceinline__ void gemm_body(
    float acc[2][8][4], const __half* A, const __half* Bh,
    uint32_t sb, int m0, int n0, int tid, int wr, int wc, int lane)
{
    auto issue = [&](int c) {
        const int kk = c * 64;
        const uint32_t dA = sb + (uint32_t)(c & 1) * 32768u;
        const uint32_t dB = dA + 16384u;
#pragma unroll
        for (int i = 0; i < 4; i++) {
            int fidx = tid + i * 256;
            int row = fidx >> 3, cc = fidx & 7;
            uint32_t off = swz128((uint32_t)(row * 128 + cc * 16));
            cpa16(dA + off, A  + (size_t)(m0 + row) * 1024 + kk + cc * 8);
            cpa16(dB + off, Bh + (size_t)(n0 + row) * 1024 + kk + cc * 8);
        }
        CP_COMMIT();
    };

    issue(0);
    for (int c = 0; c < 16; c++) {
        if (c + 1 < 16) { issue(c + 1); CP_WAIT(1); }
        else            { CP_WAIT(0); }
        __syncthreads();
        const uint32_t sA = sb + (uint32_t)(c & 1) * 32768u;
        const uint32_t sB = sA + 16384u;
#pragma unroll
        for (int s = 0; s < 4; s++) {
            uint32_t aF[2][4], bF[4][4];
            {
                const int row16 = (lane & 7) | (((lane >> 3) & 1) << 3);
                const int colb = ((lane >> 4) << 4) + s * 32;
#pragma unroll
                for (int mt = 0; mt < 2; mt++)
                    ldsm4(aF[mt], sA + swz128((uint32_t)(((wr * 32 + mt * 16 + row16) << 7) + colb)));
            }
            {
                const int row16 = (lane & 7) | ((lane >> 4) << 3);
                const int colb = (((lane >> 3) & 1) << 4) + s * 32;
#pragma unroll
                for (int p = 0; p < 4; p++)
                    ldsm4(bF[p], sB + swz128((uint32_t)(((wc * 64 + p * 16 + row16) << 7) + colb)));
            }
#pragma unroll
            for (int mt = 0; mt < 2; mt++)
#pragma unroll
                for (int nt = 0; nt < 8; nt++)
                    mma_f16(acc[mt][nt], aF[mt], &bF[nt >> 1][(nt & 1) * 2]);
        }
        __syncthreads();
    }
}

// ---------------- merged QKV projection (grid.z = 0:Q, 1:K, 2:V) -------------
__global__ void __launch_bounds__(256, 2) proj_mma(
    __half* __restrict__ G,
    const float* __restrict__ bq, const float* __restrict__ bk,
    const float* __restrict__ bv)
{
    extern __shared__ __align__(1024) char sm[];
    const uint32_t sb = smem_u32(sm);
    const int tid = threadIdx.x, wid = tid >> 5, lane = tid & 31;
    const int m0 = blockIdx.y * 128, n0 = blockIdx.x * 128;
    const int z = blockIdx.z;
    const int wr = wid >> 1, wc = wid & 1;

    const __half* A  = G + O_X + (size_t)z * SZX;
    const __half* Bh = G + O_W + (size_t)z * SZW;
    const float* bias = (z == 0) ? bq : (z == 1) ? bk : bv;

    float acc[2][8][4];
#pragma unroll
    for (int i = 0; i < 2; i++)
#pragma unroll
        for (int j = 0; j < 8; j++)
#pragma unroll
            for (int q = 0; q < 4; q++) acc[i][j][q] = 0.0f;

    gemm_body(acc, A, Bh, sb, m0, n0, tid, wr, wc, lane);

    __half* Oh = (z == 0) ? (G + O_QH) : (z == 1) ? (G + O_KH) : (G + O_VH);
    // Q scale = 1/8 * log2(e), so attention can use raw ex2
    const float scale = (z == 0) ? 0.18033688f : 1.0f;

#pragma unroll
    for (int mt = 0; mt < 2; mt++) {
        const int r0 = m0 + wr * 32 + mt * 16 + (lane >> 2);
#pragma unroll
        for (int half = 0; half < 2; half++) {
            const int m = r0 + half * 8;
            const int b = m >> 11, s = m & 2047;
#pragma unroll
            for (int nt = 0; nt < 8; nt++) {
                const int n = n0 + wc * 64 + nt * 8 + (lane & 3) * 2;
                float v0 = (acc[mt][nt][half * 2]     + __ldg(&bias[n]))     * scale;
                float v1 = (acc[mt][nt][half * 2 + 1] + __ldg(&bias[n + 1])) * scale;
                const int h = n >> 6, hd = n & 63;
                size_t addr = (((size_t)b * H_ + h) * S_ + s) * HD_ + hd;
                *(uint32_t*)&Oh[addr] = pack2h(v0, v1);
            }
        }
    }
}

// ---------------- final GEMM: out = Ch @ Wf^T + bf (fp32 out) ----------------
__global__ void __launch_bounds__(256, 2) final_mma(
    const __half* __restrict__ Ch, const __half* __restrict__ WfT,
    const float* __restrict__ bias, float* __restrict__ Of)
{
    extern __shared__ __align__(1024) char sm[];
    const uint32_t sb = smem_u32(sm);
    const int tid = threadIdx.x, wid = tid >> 5, lane = tid & 31;
    const int m0 = blockIdx.y * 128, n0 = blockIdx.x * 128;
    const int wr = wid >> 1, wc = wid & 1;

    float acc[2][8][4];
#pragma unroll
    for (int i = 0; i < 2; i++)
#pragma unroll
        for (int j = 0; j < 8; j++)
#pragma unroll
            for (int q = 0; q < 4; q++) acc[i][j][q] = 0.0f;

    gemm_body(acc, Ch, WfT, sb, m0, n0, tid, wr, wc, lane);

#pragma unroll
    for (int mt = 0; mt < 2; mt++) {
        const int r0 = m0 + wr * 32 + mt * 16 + (lane >> 2);
#pragma unroll
        for (int half = 0; half < 2; half++) {
            const int m = r0 + half * 8;
#pragma unroll
            for (int nt = 0; nt < 8; nt++) {
                const int n = n0 + wc * 64 + nt * 8 + (lane & 3) * 2;
                float2 o;
                o.x = acc[mt][nt][half * 2]     + __ldg(&bias[n]);
                o.y = acc[mt][nt][half * 2 + 1] + __ldg(&bias[n + 1]);
                *(float2*)&Of[(size_t)m * OUT_ + n] = o;
            }
        }
    }
}

// ---------------- attention: 512 threads, kv split across 2 warp groups ------
// warp wq=wid&7 -> 16 q rows; wg=wid>>3 -> kv half [wg*32, wg*32+32)
// smem: Qh 0..16K; stage st = 16K + (t&1)*16K: Kh +0, Vh +8K.  total 48KB
// epilogue: O partials reduced via smem reuse of stage area (32KB) + rs at 0
__global__ void __launch_bounds__(512, 1) attn_mma(
    const __half* __restrict__ QH, const __half* __restrict__ KH,
    const __half* __restrict__ VH, __half* __restrict__ CH)
{
    extern __shared__ __align__(1024) char sm[];
    const uint32_t sb = smem_u32(sm);
    const int tid = threadIdx.x, wid = tid >> 5, lane = tid & 31;
    const int wq = wid & 7, wg = wid >> 3;
    const int bh = blockIdx.x, q0 = blockIdx.y * 128;
    const size_t baseQ = (size_t)bh * S_ * HD_ + (size_t)q0 * HD_;
    const size_t baseK = (size_t)bh * S_ * HD_;

    auto issueKV = [&](int t) {
        const uint32_t st = sb + 16384u + (uint32_t)(t & 1) * 16384u;
        int r = tid >> 3, cc = tid & 7;          // 512 threads -> full 64x64 tile
        uint32_t off = swz128((uint32_t)(r * 128 + cc * 16));
        const size_t src = baseK + (size_t)(t * 64 + r) * 64 + cc * 8;
        cpa16(st + off,         KH + src);
        cpa16(st + 8192u + off, VH + src);
        CP_COMMIT();
    };

#pragma unroll
    for (int i = 0; i < 2; i++) {
        int fidx = tid + i * 512;
        int row = fidx >> 3, cc = fidx & 7;
        uint32_t off = swz128((uint32_t)(row * 128 + cc * 16));
        cpa16(sb + off, QH + baseQ + (size_t)row * 64 + cc * 8);
    }
    CP_COMMIT();
    issueKV(0);
    CP_WAIT(1);
    __syncthreads();

    uint32_t qh[4][4];
    {
        const int row16 = (lane & 7) | (((lane >> 3) & 1) << 3);
#pragma unroll
        for (int ds = 0; ds < 4; ds++) {
            const int colb = ((lane >> 4) << 4) + ds * 32;
            uint32_t off = swz128((uint32_t)(((wq * 16 + row16) << 7) + colb));
            ldsm4(qh[ds], sb + off);
        }
    }

    float accO[8][4];
#pragma unroll
    for (int i = 0; i < 8; i++)
#pragma unroll
        for (int j = 0; j < 4; j++) accO[i][j] = 0.0f;
    float accRS[4] = {0.f, 0.f, 0.f, 0.f};
    const uint32_t ones[2] = {0x3C003C00u, 0x3C003C00u};

    const int rowB = (lane & 7) | ((lane >> 4) << 3);
    const int colBh = ((lane >> 3) & 1) << 4;
    const int rowV = lane & 15;
    const int colV = (lane >> 4) * 16;

    for (int t = 0; t < 32; t++) {
        if (t + 1 < 32) { issueKV(t + 1); CP_WAIT(1); }
        else            { CP_WAIT(0); }
        __syncthreads();
        const uint32_t st = sb + 16384u + (uint32_t)(t & 1) * 16384u;

        // S = Qh * Kh on this group's 32 kv columns
        float accS[4][4];
#pragma unroll
        for (int i = 0; i < 4; i++)
#pragma unroll
            for (int j = 0; j < 4; j++) accS[i][j] = 0.0f;

#pragma unroll
        for (int ds = 0; ds < 4; ds++) {
            const int colb = colBh + ds * 32;
#pragma unroll
            for (int p = 0; p < 2; p++) {
                uint32_t bh_[4];
                uint32_t off = swz128((uint32_t)(((wg * 32 + p * 16 + rowB) << 7) + colb));
                ldsm4(bh_, st + off);
#pragma unroll
                for (int half = 0; half < 2; half++)
                    mma_f16(accS[p * 2 + half], qh[ds], &bh_[half * 2]);
            }
        }

        // exp via raw ex2, pack P single-plane fp16
        uint32_t pk[4][2];
#pragma unroll
        for (int nt = 0; nt < 4; nt++) {
            float e0 = ex2f(accS[nt][0]);
            float e1 = ex2f(accS[nt][1]);
            float e2 = ex2f(accS[nt][2]);
            float e3 = ex2f(accS[nt][3]);
            pk[nt][0] = pack2h(e0, e1);
            pk[nt][1] = pack2h(e2, e3);
        }

        // O += P * Vh ; rowsum += P * ones   (this group's 32 kv rows of V)
#pragma unroll
        for (int p = 0; p < 2; p++) {
            uint32_t ah[4];
            ah[0] = pk[2*p][0];   ah[1] = pk[2*p][1];
            ah[2] = pk[2*p+1][0]; ah[3] = pk[2*p+1][1];
            mma_f16(accRS, ah, ones);
#pragma unroll
            for (int jj = 0; jj < 4; jj++) {
                uint32_t vh_[4];
                uint32_t off = swz128((uint32_t)(((wg * 32 + p * 16 + rowV) << 7) + jj * 32 + colV));
                ldsm4t(vh_, st + 8192u + off);
#pragma unroll
                for (int half = 0; half < 2; half++)
                    mma_f16(accO[jj * 2 + half], ah, &vh_[half * 2]);
            }
        }
        __syncthreads();
    }

    // cross-group reduction: wg0 writes partials into smem, wg1 combines
    float* red = (float*)(sm + 16384);       // 128 x 64 fp32 = 32KB (stage reuse)
    float* rsb = (float*)sm;                 // 128 fp32
    __syncthreads();

    const int rbase = wq * 16 + (lane >> 2);
    if (wg == 0) {
        if ((lane & 3) == 0) {
            rsb[rbase]     = accRS[0];
            rsb[rbase + 8] = accRS[2];
        }
#pragma unroll
        for (int half = 0; half < 2; half++) {
            const int row = rbase + half * 8;
#pragma unroll
            for (int nt = 0; nt < 8; nt++) {
                const int col = nt * 8 + (lane & 3) * 2;
                float2 v = {accO[nt][half * 2], accO[nt][half * 2 + 1]};
                *(float2*)&red[row * 64 + col] = v;
            }
        }
    }
    __syncthreads();

    if (wg == 1) {
        const float inv0 = 1.0f / (1.0f + accRS[0] + rsb[rbase]);
        const float inv1 = 1.0f / (1.0f + accRS[2] + rsb[rbase + 8]);
        const int b = bh >> 4, h = bh & 15;
#pragma unroll
        for (int half = 0; half < 2; half++) {
            const int row = rbase + half * 8;
            const int q = q0 + row;
            const float inv = half ? inv1 : inv0;
            const size_t rowb = ((size_t)b * S_ + q) * D_ + h * HD_;
#pragma unroll
            for (int nt = 0; nt < 8; nt++) {
                const int col = nt * 8 + (lane & 3) * 2;
                float2 part = *(const float2*)&red[row * 64 + col];
                *(uint32_t*)&CH[rowb + col] =
                    pack2h((accO[nt][half * 2] + part.x) * inv,
                           (accO[nt][half * 2 + 1] + part.y) * inv);
            }
        }
    }
}

// ---------------- host ----------------
extern "C" void kernel_launch(void* const* d_in, const int* in_sizes, int n_in,
                              void* d_out, int out_size)
{
    (void)in_sizes; (void)n_in; (void)out_size;
    const float* query = (const float*)d_in[0];
    const float* key   = (const float*)d_in[1];
    const float* value = (const float*)d_in[2];
    const float* Wq = (const float*)d_in[3];
    const float* bq = (const float*)d_in[4];
    const float* Wk = (const float*)d_in[5];
    const float* bk = (const float*)d_in[6];
    const float* Wv = (const float*)d_in[7];
    const float* bv = (const float*)d_in[8];
    const float* Wf = (const float*)d_in[9];
    const float* bf = (const float*)d_in[10];

    __half* G;
    cudaGetSymbolAddress((void**)&G, g_hf);

    const int n4 = (int)(SZX / 4);
    cvt3_h<<<dim3(n4 / 256, 3), 256>>>(query, key, value, G, n4);
    transpose4_h<<<dim3(32, 32, 4), 256>>>(Wq, Wk, Wv, Wf, G);

    const int gsm = 65536;
    cudaFuncSetAttribute(proj_mma,  cudaFuncAttributeMaxDynamicSharedMemorySize, gsm);
    cudaFuncSetAttribute(final_mma, cudaFuncAttributeMaxDynamicSharedMemorySize, gsm);

    proj_mma<<<dim3(D_ / 128, M_ / 128, 3), 256, gsm>>>(G, bq, bk, bv);

    const int asm_ = 16384 + 2 * 16384;  // 49152
    cudaFuncSetAttribute(attn_mma, cudaFuncAttributeMaxDynamicSharedMemorySize, asm_);
    attn_mma<<<dim3(BH_, S_ / 128), 512, asm_>>>(
        G + O_QH, G + O_KH, G + O_VH, G + O_CH);

    final_mma<<<dim3(OUT_ / 128, M_ / 128), 256, gsm>>>(
        G + O_CH, G + O_WF, bf, (float*)d_out);
}

// round 14
// speedup vs baseline: 1.0778x; 1.0778x over previous
#include <cuda_runtime.h>
#include <cuda_fp16.h>
#include <cstdint>

#define B_ 4
#define S_ 2048
#define D_ 1024
#define H_ 16
#define HD_ 64
#define OUT_ 256
#define M_ (B_*S_)
#define BH_ (B_*H_)

static constexpr size_t SZX = (size_t)M_ * D_;
static constexpr size_t SZW = (size_t)D_ * D_;
static constexpr size_t SZF = (size_t)D_ * OUT_;

static constexpr size_t O_X   = 0;                      // [Xq,Xk,Xv] hi, stride SZX
static constexpr size_t O_W   = O_X + 3 * SZX;          // [Wq,Wk,Wv]^T, stride SZW
static constexpr size_t O_WF  = O_W + 3 * SZW;
static constexpr size_t O_QH  = O_WF + SZF;
static constexpr size_t O_KH  = O_QH + SZX;
static constexpr size_t O_VH  = O_KH + SZX;
static constexpr size_t O_CH  = O_VH + SZX;
static constexpr size_t TOTAL_HF = O_CH + SZX;

__device__ __half g_hf[TOTAL_HF];

// ---------------- helpers ----------------
__device__ __forceinline__ uint32_t smem_u32(const void* p) {
    uint32_t a;
    asm("{ .reg .u64 t; cvta.to.shared.u64 t, %1; cvt.u32.u64 %0, t; }" : "=r"(a) : "l"(p));
    return a;
}
__device__ __forceinline__ void ldsm4(uint32_t* r, uint32_t a) {
    asm volatile("ldmatrix.sync.aligned.m8n8.x4.shared.b16 {%0,%1,%2,%3}, [%4];"
        : "=r"(r[0]), "=r"(r[1]), "=r"(r[2]), "=r"(r[3]) : "r"(a));
}
__device__ __forceinline__ void ldsm4t(uint32_t* r, uint32_t a) {
    asm volatile("ldmatrix.sync.aligned.m8n8.x4.trans.shared.b16 {%0,%1,%2,%3}, [%4];"
        : "=r"(r[0]), "=r"(r[1]), "=r"(r[2]), "=r"(r[3]) : "r"(a));
}
__device__ __forceinline__ void mma_f16(float* d, const uint32_t* a, const uint32_t* b) {
    asm volatile("mma.sync.aligned.m16n8k16.row.col.f32.f16.f16.f32 "
        "{%0,%1,%2,%3}, {%4,%5,%6,%7}, {%8,%9}, {%0,%1,%2,%3};"
        : "+f"(d[0]), "+f"(d[1]), "+f"(d[2]), "+f"(d[3])
        : "r"(a[0]), "r"(a[1]), "r"(a[2]), "r"(a[3]), "r"(b[0]), "r"(b[1]));
}
__device__ __forceinline__ void cpa16(uint32_t dst, const void* src) {
    asm volatile("cp.async.cg.shared.global [%0], [%1], 16;" :: "r"(dst), "l"(src));
}
#define CP_COMMIT() asm volatile("cp.async.commit_group;" ::: "memory")
#define CP_WAIT(n)  asm volatile("cp.async.wait_group %0;" :: "n"(n) : "memory")

__device__ __forceinline__ uint32_t swz128(uint32_t o) { return o ^ ((o >> 3) & 0x70); }
__device__ __forceinline__ uint32_t pack2h(float a, float b) {
    __half2 t = __floats2half2_rn(a, b);
    return *(uint32_t*)&t;
}
__device__ __forceinline__ float ex2f(float x) {
    float r;
    asm("ex2.approx.f32 %0, %1;" : "=f"(r) : "f"(x));
    return r;
}

// ---------------- conversions ----------------
__global__ void cvt3_h(const float* __restrict__ q, const float* __restrict__ k,
                       const float* __restrict__ v, __half* __restrict__ G, int n4) {
    const int z = blockIdx.y;
    const float* x = (z == 0) ? q : (z == 1) ? k : v;
    __half* hi = G + O_X + (size_t)z * SZX;
    int i = blockIdx.x * blockDim.x + threadIdx.x;
    if (i >= n4) return;
    float4 vv = ((const float4*)x)[i];
    ((uint32_t*)hi)[i*2]   = pack2h(vv.x, vv.y);
    ((uint32_t*)hi)[i*2+1] = pack2h(vv.z, vv.w);
}

// W [K][N] -> W^T [N][K] fp16; z=0..2: Wq/Wk/Wv (N=1024), z=3: Wf (N=256)
__global__ void transpose4_h(const float* __restrict__ Wq, const float* __restrict__ Wk,
                             const float* __restrict__ Wv, const float* __restrict__ Wf,
                             __half* __restrict__ G) {
    __shared__ float t[32][33];
    const int z = blockIdx.z;
    const float* W = (z == 0) ? Wq : (z == 1) ? Wk : (z == 2) ? Wv : Wf;
    __half* Th = (z < 3) ? (G + O_W + (size_t)z * SZW) : (G + O_WF);
    const int Ndim = (z < 3) ? D_ : OUT_;
    const int n0 = blockIdx.x * 32, k0 = blockIdx.y * 32;
    if (n0 >= Ndim) return;
    const int tx = threadIdx.x & 31, ty = threadIdx.x >> 5;
#pragma unroll
    for (int i = 0; i < 32; i += 8)
        t[ty + i][tx] = W[(size_t)(k0 + ty + i) * Ndim + n0 + tx];
    __syncthreads();
#pragma unroll
    for (int i = 0; i < 32; i += 8)
        Th[(size_t)(n0 + ty + i) * D_ + k0 + tx] = __float2half_rn(t[tx][ty + i]);
}

// ---------------- GEMM mainloop: acc += A[128,1024] @ B[128 rows,1024]^T -----
__device__ __forceinline__ void gemm_body(
    float acc[2][8][4], const __half* A, const __half* Bh,
    uint32_t sb, int m0, int n0, int tid, int wr, int wc, int lane)
{
    auto issue = [&](int c) {
        const int kk = c * 64;
        const uint32_t dA = sb + (uint32_t)(c & 1) * 32768u;
        const uint32_t dB = dA + 16384u;
#pragma unroll
        for (int i = 0; i < 4; i++) {
            int fidx = tid + i * 256;
            int row = fidx >> 3, cc = fidx & 7;
            uint32_t off = swz128((uint32_t)(row * 128 + cc * 16));
            cpa16(dA + off, A  + (size_t)(m0 + row) * 1024 + kk + cc * 8);
            cpa16(dB + off, Bh + (size_t)(n0 + row) * 1024 + kk + cc * 8);
        }
        CP_COMMIT();
    };

    issue(0);
    for (int c = 0; c < 16; c++) {
        if (c + 1 < 16) { issue(c + 1); CP_WAIT(1); }
        else            { CP_WAIT(0); }
        __syncthreads();
        const uint32_t sA = sb + (uint32_t)(c & 1) * 32768u;
        const uint32_t sB = sA + 16384u;
#pragma unroll
        for (int s = 0; s < 4; s++) {
            uint32_t aF[2][4], bF[4][4];
            {
                const int row16 = (lane & 7) | (((lane >> 3) & 1) << 3);
                const int colb = ((lane >> 4) << 4) + s * 32;
#pragma unroll
                for (int mt = 0; mt < 2; mt++)
                    ldsm4(aF[mt], sA + swz128((uint32_t)(((wr * 32 + mt * 16 + row16) << 7) + colb)));
            }
            {
                const int row16 = (lane & 7) | ((lane >> 4) << 3);
                const int colb = (((lane >> 3) & 1) << 4) + s * 32;
#pragma unroll
                for (int p = 0; p < 4; p++)
                    ldsm4(bF[p], sB + swz128((uint32_t)(((wc * 64 + p * 16 + row16) << 7) + colb)));
            }
#pragma unroll
            for (int mt = 0; mt < 2; mt++)
#pragma unroll
                for (int nt = 0; nt < 8; nt++)
                    mma_f16(acc[mt][nt], aF[mt], &bF[nt >> 1][(nt & 1) * 2]);
        }
        __syncthreads();
    }
}

// ---------------- merged QKV projection (grid.z = 0:Q, 1:K, 2:V) -------------
__global__ void __launch_bounds__(256, 2) proj_mma(
    __half* __restrict__ G,
    const float* __restrict__ bq, const float* __restrict__ bk,
    const float* __restrict__ bv)
{
    extern __shared__ __align__(1024) char sm[];
    const uint32_t sb = smem_u32(sm);
    const int tid = threadIdx.x, wid = tid >> 5, lane = tid & 31;
    const int m0 = blockIdx.y * 128, n0 = blockIdx.x * 128;
    const int z = blockIdx.z;
    const int wr = wid >> 1, wc = wid & 1;

    const __half* A  = G + O_X + (size_t)z * SZX;
    const __half* Bh = G + O_W + (size_t)z * SZW;
    const float* bias = (z == 0) ? bq : (z == 1) ? bk : bv;

    float acc[2][8][4];
#pragma unroll
    for (int i = 0; i < 2; i++)
#pragma unroll
        for (int j = 0; j < 8; j++)
#pragma unroll
            for (int q = 0; q < 4; q++) acc[i][j][q] = 0.0f;

    gemm_body(acc, A, Bh, sb, m0, n0, tid, wr, wc, lane);

    __half* Oh = (z == 0) ? (G + O_QH) : (z == 1) ? (G + O_KH) : (G + O_VH);
    // Q scale = 1/8 * log2(e), so attention can use raw ex2
    const float scale = (z == 0) ? 0.18033688f : 1.0f;

#pragma unroll
    for (int mt = 0; mt < 2; mt++) {
        const int r0 = m0 + wr * 32 + mt * 16 + (lane >> 2);
#pragma unroll
        for (int half = 0; half < 2; half++) {
            const int m = r0 + half * 8;
            const int b = m >> 11, s = m & 2047;
#pragma unroll
            for (int nt = 0; nt < 8; nt++) {
                const int n = n0 + wc * 64 + nt * 8 + (lane & 3) * 2;
                float v0 = (acc[mt][nt][half * 2]     + __ldg(&bias[n]))     * scale;
                float v1 = (acc[mt][nt][half * 2 + 1] + __ldg(&bias[n + 1])) * scale;
                const int h = n >> 6, hd = n & 63;
                size_t addr = (((size_t)b * H_ + h) * S_ + s) * HD_ + hd;
                *(uint32_t*)&Oh[addr] = pack2h(v0, v1);
            }
        }
    }
}

// ---------------- final GEMM: out = Ch @ Wf^T + bf (fp32 out) ----------------
__global__ void __launch_bounds__(256, 2) final_mma(
    const __half* __restrict__ Ch, const __half* __restrict__ WfT,
    const float* __restrict__ bias, float* __restrict__ Of)
{
    extern __shared__ __align__(1024) char sm[];
    const uint32_t sb = smem_u32(sm);
    const int tid = threadIdx.x, wid = tid >> 5, lane = tid & 31;
    const int m0 = blockIdx.y * 128, n0 = blockIdx.x * 128;
    const int wr = wid >> 1, wc = wid & 1;

    float acc[2][8][4];
#pragma unroll
    for (int i = 0; i < 2; i++)
#pragma unroll
        for (int j = 0; j < 8; j++)
#pragma unroll
            for (int q = 0; q < 4; q++) acc[i][j][q] = 0.0f;

    gemm_body(acc, Ch, WfT, sb, m0, n0, tid, wr, wc, lane);

#pragma unroll
    for (int mt = 0; mt < 2; mt++) {
        const int r0 = m0 + wr * 32 + mt * 16 + (lane >> 2);
#pragma unroll
        for (int half = 0; half < 2; half++) {
            const int m = r0 + half * 8;
#pragma unroll
            for (int nt = 0; nt < 8; nt++) {
                const int n = n0 + wc * 64 + nt * 8 + (lane & 3) * 2;
                float2 o;
                o.x = acc[mt][nt][half * 2]     + __ldg(&bias[n]);
                o.y = acc[mt][nt][half * 2 + 1] + __ldg(&bias[n + 1]);
                *(float2*)&Of[(size_t)m * OUT_ + n] = o;
            }
        }
    }
}

// ---------------- attention: kv-stage 128 rows, two 64-kv inner passes -------
// 256 threads, 8 warps x 16 q rows, full kv width per pass.
// smem: Qh 0..16K; stage st = 16K + (ts&1)*32K: Kh[128][64] +0, Vh +16K.
// total 80KB -> 2 CTAs/SM.  Syncs: 16 (one per 128-kv stage).
__global__ void __launch_bounds__(256, 2) attn_mma(
    const __half* __restrict__ QH, const __half* __restrict__ KH,
    const __half* __restrict__ VH, __half* __restrict__ CH)
{
    extern __shared__ __align__(1024) char sm[];
    const uint32_t sb = smem_u32(sm);
    const int tid = threadIdx.x, wid = tid >> 5, lane = tid & 31;
    const int bh = blockIdx.x, q0 = blockIdx.y * 128;
    const size_t baseQ = (size_t)bh * S_ * HD_ + (size_t)q0 * HD_;
    const size_t baseK = (size_t)bh * S_ * HD_;

    auto issueKV = [&](int ts) {
        const uint32_t st = sb + 16384u + (uint32_t)(ts & 1) * 32768u;
#pragma unroll
        for (int i = 0; i < 4; i++) {
            int fidx = tid + i * 256;            // 0..1023 -> 128 rows x 8 col-chunks
            int r = fidx >> 3, cc = fidx & 7;
            uint32_t off = swz128((uint32_t)(r * 128 + cc * 16));
            const size_t src = baseK + (size_t)(ts * 128 + r) * 64 + cc * 8;
            cpa16(st + off,          KH + src);
            cpa16(st + 16384u + off, VH + src);
        }
        CP_COMMIT();
    };

#pragma unroll
    for (int i = 0; i < 4; i++) {
        int fidx = tid + i * 256;
        int row = fidx >> 3, cc = fidx & 7;
        uint32_t off = swz128((uint32_t)(row * 128 + cc * 16));
        cpa16(sb + off, QH + baseQ + (size_t)row * 64 + cc * 8);
    }
    CP_COMMIT();
    issueKV(0);
    CP_WAIT(1);
    __syncthreads();

    uint32_t qh[4][4];
    {
        const int row16 = (lane & 7) | (((lane >> 3) & 1) << 3);
#pragma unroll
        for (int ds = 0; ds < 4; ds++) {
            const int colb = ((lane >> 4) << 4) + ds * 32;
            uint32_t off = swz128((uint32_t)(((wid * 16 + row16) << 7) + colb));
            ldsm4(qh[ds], sb + off);
        }
    }

    float accO[8][4];
#pragma unroll
    for (int i = 0; i < 8; i++)
#pragma unroll
        for (int j = 0; j < 4; j++) accO[i][j] = 0.0f;
    float accRS[4] = {0.f, 0.f, 0.f, 0.f};       // rowsum via P @ ones
    const uint32_t ones[2] = {0x3C003C00u, 0x3C003C00u};

    const int rowB = (lane & 7) | ((lane >> 4) << 3);
    const int colBh = ((lane >> 3) & 1) << 4;
    const int rowV = lane & 15;
    const int colV = (lane >> 4) * 16;

    for (int ts = 0; ts < 16; ts++) {
        if (ts + 1 < 16) { issueKV(ts + 1); CP_WAIT(1); }
        else             { CP_WAIT(0); }
        __syncthreads();
        const uint32_t st = sb + 16384u + (uint32_t)(ts & 1) * 32768u;

#pragma unroll
        for (int kb = 0; kb < 2; kb++) {
            const int kvo = kb * 64;             // row offset within the 128-row stage

            // S = Qh * Kh  (scale*log2e pre-folded into Q)
            float accS[8][4];
#pragma unroll
            for (int i = 0; i < 8; i++)
#pragma unroll
                for (int j = 0; j < 4; j++) accS[i][j] = 0.0f;

#pragma unroll
            for (int ds = 0; ds < 4; ds++) {
                const int colb = colBh + ds * 32;
#pragma unroll
                for (int p = 0; p < 4; p++) {
                    uint32_t bh_[4];
                    uint32_t off = swz128((uint32_t)(((kvo + p * 16 + rowB) << 7) + colb));
                    ldsm4(bh_, st + off);
#pragma unroll
                    for (int half = 0; half < 2; half++)
                        mma_f16(accS[p * 2 + half], qh[ds], &bh_[half * 2]);
                }
            }

            // exp via raw ex2, pack P single-plane fp16
            uint32_t pk[8][2];
#pragma unroll
            for (int nt = 0; nt < 8; nt++) {
                float e0 = ex2f(accS[nt][0]);
                float e1 = ex2f(accS[nt][1]);
                float e2 = ex2f(accS[nt][2]);
                float e3 = ex2f(accS[nt][3]);
                pk[nt][0] = pack2h(e0, e1);
                pk[nt][1] = pack2h(e2, e3);
            }

            // O += P * Vh ; rowsum += P * ones
#pragma unroll
            for (int p = 0; p < 4; p++) {
                uint32_t ah[4];
                ah[0] = pk[2*p][0];   ah[1] = pk[2*p][1];
                ah[2] = pk[2*p+1][0]; ah[3] = pk[2*p+1][1];
                mma_f16(accRS, ah, ones);
#pragma unroll
                for (int jj = 0; jj < 4; jj++) {
                    uint32_t vh_[4];
                    uint32_t off = swz128((uint32_t)(((kvo + p * 16 + rowV) << 7) + jj * 32 + colV));
                    ldsm4t(vh_, st + 16384u + off);
#pragma unroll
                    for (int half = 0; half < 2; half++)
                        mma_f16(accO[jj * 2 + half], ah, &vh_[half * 2]);
                }
            }
        }
        __syncthreads();
    }

    // accRS[0] = rowsum(row lane>>2), accRS[2] = rowsum(row lane>>2 + 8)
    const float inv0 = 1.0f / (1.0f + accRS[0]);
    const float inv1 = 1.0f / (1.0f + accRS[2]);

    const int b = bh >> 4, h = bh & 15;
    const int qA = q0 + wid * 16 + (lane >> 2);
#pragma unroll
    for (int half = 0; half < 2; half++) {
        const int q = qA + half * 8;
        const float inv = half ? inv1 : inv0;
        const size_t rowb = ((size_t)b * S_ + q) * D_ + h * HD_;
#pragma unroll
        for (int nt = 0; nt < 8; nt++) {
            const int col = nt * 8 + (lane & 3) * 2;
            *(uint32_t*)&CH[rowb + col] =
                pack2h(accO[nt][half * 2] * inv, accO[nt][half * 2 + 1] * inv);
        }
    }
}

// ---------------- host ----------------
extern "C" void kernel_launch(void* const* d_in, const int* in_sizes, int n_in,
                              void* d_out, int out_size)
{
    (void)in_sizes; (void)n_in; (void)out_size;
    const float* query = (const float*)d_in[0];
    const float* key   = (const float*)d_in[1];
    const float* value = (const float*)d_in[2];
    const float* Wq = (const float*)d_in[3];
    const float* bq = (const float*)d_in[4];
    const float* Wk = (const float*)d_in[5];
    const float* bk = (const float*)d_in[6];
    const float* Wv = (const float*)d_in[7];
    const float* bv = (const float*)d_in[8];
    const float* Wf = (const float*)d_in[9];
    const float* bf = (const float*)d_in[10];

    __half* G;
    cudaGetSymbolAddress((void**)&G, g_hf);

    const int n4 = (int)(SZX / 4);
    cvt3_h<<<dim3(n4 / 256, 3), 256>>>(query, key, value, G, n4);
    transpose4_h<<<dim3(32, 32, 4), 256>>>(Wq, Wk, Wv, Wf, G);

    const int gsm = 65536;
    cudaFuncSetAttribute(proj_mma,  cudaFuncAttributeMaxDynamicSharedMemorySize, gsm);
    cudaFuncSetAttribute(final_mma, cudaFuncAttributeMaxDynamicSharedMemorySize, gsm);

    proj_mma<<<dim3(D_ / 128, M_ / 128, 3), 256, gsm>>>(G, bq, bk, bv);

    const int asm_ = 16384 + 2 * 32768;  // 81920
    cudaFuncSetAttribute(attn_mma, cudaFuncAttributeMaxDynamicSharedMemorySize, asm_);
    attn_mma<<<dim3(BH_, S_ / 128), 256, asm_>>>(
        G + O_QH, G + O_KH, G + O_VH, G + O_CH);

    final_mma<<<dim3(OUT_ / 128, M_ / 128), 256, gsm>>>(
        G + O_CH, G + O_WF, bf, (float*)d_out);
}

// round 15
// speedup vs baseline: 1.1021x; 1.0226x over previous
#include <cuda_runtime.h>
#include <cuda_fp16.h>
#include <cstdint>

#define B_ 4
#define S_ 2048
#define D_ 1024
#define H_ 16
#define HD_ 64
#define OUT_ 256
#define M_ (B_*S_)
#define BH_ (B_*H_)

static constexpr size_t SZX = (size_t)M_ * D_;
static constexpr size_t SZW = (size_t)D_ * D_;
static constexpr size_t SZF = (size_t)D_ * OUT_;

static constexpr size_t O_X   = 0;                      // [Xq,Xk,Xv] hi, stride SZX
static constexpr size_t O_W   = O_X + 3 * SZX;          // [Wq,Wk,Wv]^T, stride SZW
static constexpr size_t O_WF  = O_W + 3 * SZW;
static constexpr size_t O_QH  = O_WF + SZF;
static constexpr size_t O_KH  = O_QH + SZX;
static constexpr size_t O_VH  = O_KH + SZX;
static constexpr size_t O_CH  = O_VH + SZX;
static constexpr size_t TOTAL_HF = O_CH + SZX;

__device__ __half g_hf[TOTAL_HF];

// ---------------- helpers ----------------
__device__ __forceinline__ uint32_t smem_u32(const void* p) {
    uint32_t a;
    asm("{ .reg .u64 t; cvta.to.shared.u64 t, %1; cvt.u32.u64 %0, t; }" : "=r"(a) : "l"(p));
    return a;
}
__device__ __forceinline__ void ldsm4(uint32_t* r, uint32_t a) {
    asm volatile("ldmatrix.sync.aligned.m8n8.x4.shared.b16 {%0,%1,%2,%3}, [%4];"
        : "=r"(r[0]), "=r"(r[1]), "=r"(r[2]), "=r"(r[3]) : "r"(a));
}
__device__ __forceinline__ void ldsm4t(uint32_t* r, uint32_t a) {
    asm volatile("ldmatrix.sync.aligned.m8n8.x4.trans.shared.b16 {%0,%1,%2,%3}, [%4];"
        : "=r"(r[0]), "=r"(r[1]), "=r"(r[2]), "=r"(r[3]) : "r"(a));
}
__device__ __forceinline__ void mma_f16(float* d, const uint32_t* a, const uint32_t* b) {
    asm volatile("mma.sync.aligned.m16n8k16.row.col.f32.f16.f16.f32 "
        "{%0,%1,%2,%3}, {%4,%5,%6,%7}, {%8,%9}, {%0,%1,%2,%3};"
        : "+f"(d[0]), "+f"(d[1]), "+f"(d[2]), "+f"(d[3])
        : "r"(a[0]), "r"(a[1]), "r"(a[2]), "r"(a[3]), "r"(b[0]), "r"(b[1]));
}
__device__ __forceinline__ void cpa16(uint32_t dst, const void* src) {
    asm volatile("cp.async.cg.shared.global [%0], [%1], 16;" :: "r"(dst), "l"(src));
}
#define CP_COMMIT() asm volatile("cp.async.commit_group;" ::: "memory")
#define CP_WAIT(n)  asm volatile("cp.async.wait_group %0;" :: "n"(n) : "memory")

__device__ __forceinline__ uint32_t swz128(uint32_t o) { return o ^ ((o >> 3) & 0x70); }
__device__ __forceinline__ uint32_t pack2h(float a, float b) {
    __half2 t = __floats2half2_rn(a, b);
    return *(uint32_t*)&t;
}
// packed fp16 exp2: one MUFU op for two elements, output already packed
__device__ __forceinline__ uint32_t h2ex2(uint32_t x) {
    uint32_t r;
    asm("ex2.approx.f16x2 %0, %1;" : "=r"(r) : "r"(x));
    return r;
}

// ---------------- conversions ----------------
__global__ void cvt3_h(const float* __restrict__ q, const float* __restrict__ k,
                       const float* __restrict__ v, __half* __restrict__ G, int n4) {
    const int z = blockIdx.y;
    const float* x = (z == 0) ? q : (z == 1) ? k : v;
    __half* hi = G + O_X + (size_t)z * SZX;
    int i = blockIdx.x * blockDim.x + threadIdx.x;
    if (i >= n4) return;
    float4 vv = ((const float4*)x)[i];
    ((uint32_t*)hi)[i*2]   = pack2h(vv.x, vv.y);
    ((uint32_t*)hi)[i*2+1] = pack2h(vv.z, vv.w);
}

// W [K][N] -> W^T [N][K] fp16; z=0..2: Wq/Wk/Wv (N=1024), z=3: Wf (N=256)
__global__ void transpose4_h(const float* __restrict__ Wq, const float* __restrict__ Wk,
                             const float* __restrict__ Wv, const float* __restrict__ Wf,
                             __half* __restrict__ G) {
    __shared__ float t[32][33];
    const int z = blockIdx.z;
    const float* W = (z == 0) ? Wq : (z == 1) ? Wk : (z == 2) ? Wv : Wf;
    __half* Th = (z < 3) ? (G + O_W + (size_t)z * SZW) : (G + O_WF);
    const int Ndim = (z < 3) ? D_ : OUT_;
    const int n0 = blockIdx.x * 32, k0 = blockIdx.y * 32;
    if (n0 >= Ndim) return;
    const int tx = threadIdx.x & 31, ty = threadIdx.x >> 5;
#pragma unroll
    for (int i = 0; i < 32; i += 8)
        t[ty + i][tx] = W[(size_t)(k0 + ty + i) * Ndim + n0 + tx];
    __syncthreads();
#pragma unroll
    for (int i = 0; i < 32; i += 8)
        Th[(size_t)(n0 + ty + i) * D_ + k0 + tx] = __float2half_rn(t[tx][ty + i]);
}

// ---------------- GEMM mainloop: acc += A[128,1024] @ B[128 rows,1024]^T -----
__device__ __forceinline__ void gemm_body(
    float acc[2][8][4], const __half* A, const __half* Bh,
    uint32_t sb, int m0, int n0, int tid, int wr, int wc, int lane)
{
    auto issue = [&](int c) {
        const int kk = c * 64;
        const uint32_t dA = sb + (uint32_t)(c & 1) * 32768u;
        const uint32_t dB = dA + 16384u;
#pragma unroll
        for (int i = 0; i < 4; i++) {
            int fidx = tid + i * 256;
            int row = fidx >> 3, cc = fidx & 7;
            uint32_t off = swz128((uint32_t)(row * 128 + cc * 16));
            cpa16(dA + off, A  + (size_t)(m0 + row) * 1024 + kk + cc * 8);
            cpa16(dB + off, Bh + (size_t)(n0 + row) * 1024 + kk + cc * 8);
        }
        CP_COMMIT();
    };

    issue(0);
    for (int c = 0; c < 16; c++) {
        if (c + 1 < 16) { issue(c + 1); CP_WAIT(1); }
        else            { CP_WAIT(0); }
        __syncthreads();
        const uint32_t sA = sb + (uint32_t)(c & 1) * 32768u;
        const uint32_t sB = sA + 16384u;
#pragma unroll
        for (int s = 0; s < 4; s++) {
            uint32_t aF[2][4], bF[4][4];
            {
                const int row16 = (lane & 7) | (((lane >> 3) & 1) << 3);
                const int colb = ((lane >> 4) << 4) + s * 32;
#pragma unroll
                for (int mt = 0; mt < 2; mt++)
                    ldsm4(aF[mt], sA + swz128((uint32_t)(((wr * 32 + mt * 16 + row16) << 7) + colb)));
            }
            {
                const int row16 = (lane & 7) | ((lane >> 4) << 3);
                const int colb = (((lane >> 3) & 1) << 4) + s * 32;
#pragma unroll
                for (int p = 0; p < 4; p++)
                    ldsm4(bF[p], sB + swz128((uint32_t)(((wc * 64 + p * 16 + row16) << 7) + colb)));
            }
#pragma unroll
            for (int mt = 0; mt < 2; mt++)
#pragma unroll
                for (int nt = 0; nt < 8; nt++)
                    mma_f16(acc[mt][nt], aF[mt], &bF[nt >> 1][(nt & 1) * 2]);
        }
        __syncthreads();
    }
}

// ---------------- merged QKV projection (grid.z = 0:Q, 1:K, 2:V) -------------
__global__ void __launch_bounds__(256, 2) proj_mma(
    __half* __restrict__ G,
    const float* __restrict__ bq, const float* __restrict__ bk,
    const float* __restrict__ bv)
{
    extern __shared__ __align__(1024) char sm[];
    const uint32_t sb = smem_u32(sm);
    const int tid = threadIdx.x, wid = tid >> 5, lane = tid & 31;
    const int m0 = blockIdx.y * 128, n0 = blockIdx.x * 128;
    const int z = blockIdx.z;
    const int wr = wid >> 1, wc = wid & 1;

    const __half* A  = G + O_X + (size_t)z * SZX;
    const __half* Bh = G + O_W + (size_t)z * SZW;
    const float* bias = (z == 0) ? bq : (z == 1) ? bk : bv;

    float acc[2][8][4];
#pragma unroll
    for (int i = 0; i < 2; i++)
#pragma unroll
        for (int j = 0; j < 8; j++)
#pragma unroll
            for (int q = 0; q < 4; q++) acc[i][j][q] = 0.0f;

    gemm_body(acc, A, Bh, sb, m0, n0, tid, wr, wc, lane);

    __half* Oh = (z == 0) ? (G + O_QH) : (z == 1) ? (G + O_KH) : (G + O_VH);
    // Q scale = 1/8 * log2(e), so attention can use raw ex2
    const float scale = (z == 0) ? 0.18033688f : 1.0f;

#pragma unroll
    for (int mt = 0; mt < 2; mt++) {
        const int r0 = m0 + wr * 32 + mt * 16 + (lane >> 2);
#pragma unroll
        for (int half = 0; half < 2; half++) {
            const int m = r0 + half * 8;
            const int b = m >> 11, s = m & 2047;
#pragma unroll
            for (int nt = 0; nt < 8; nt++) {
                const int n = n0 + wc * 64 + nt * 8 + (lane & 3) * 2;
                float v0 = (acc[mt][nt][half * 2]     + __ldg(&bias[n]))     * scale;
                float v1 = (acc[mt][nt][half * 2 + 1] + __ldg(&bias[n + 1])) * scale;
                const int h = n >> 6, hd = n & 63;
                size_t addr = (((size_t)b * H_ + h) * S_ + s) * HD_ + hd;
                *(uint32_t*)&Oh[addr] = pack2h(v0, v1);
            }
        }
    }
}

// ---------------- final GEMM: out = Ch @ Wf^T + bf (fp32 out) ----------------
__global__ void __launch_bounds__(256, 2) final_mma(
    const __half* __restrict__ Ch, const __half* __restrict__ WfT,
    const float* __restrict__ bias, float* __restrict__ Of)
{
    extern __shared__ __align__(1024) char sm[];
    const uint32_t sb = smem_u32(sm);
    const int tid = threadIdx.x, wid = tid >> 5, lane = tid & 31;
    const int m0 = blockIdx.y * 128, n0 = blockIdx.x * 128;
    const int wr = wid >> 1, wc = wid & 1;

    float acc[2][8][4];
#pragma unroll
    for (int i = 0; i < 2; i++)
#pragma unroll
        for (int j = 0; j < 8; j++)
#pragma unroll
            for (int q = 0; q < 4; q++) acc[i][j][q] = 0.0f;

    gemm_body(acc, Ch, WfT, sb, m0, n0, tid, wr, wc, lane);

#pragma unroll
    for (int mt = 0; mt < 2; mt++) {
        const int r0 = m0 + wr * 32 + mt * 16 + (lane >> 2);
#pragma unroll
        for (int half = 0; half < 2; half++) {
            const int m = r0 + half * 8;
#pragma unroll
            for (int nt = 0; nt < 8; nt++) {
                const int n = n0 + wc * 64 + nt * 8 + (lane & 3) * 2;
                float2 o;
                o.x = acc[mt][nt][half * 2]     + __ldg(&bias[n]);
                o.y = acc[mt][nt][half * 2 + 1] + __ldg(&bias[n + 1]);
                *(float2*)&Of[(size_t)m * OUT_ + n] = o;
            }
        }
    }
}

// ---------------- attention: kv-stage 128 rows, two 64-kv inner passes -------
// 256 threads, 8 warps x 16 q rows, full kv width per pass.
// smem: Qh 0..16K; stage st = 16K + (ts&1)*32K: Kh[128][64] +0, Vh +16K.
// total 80KB -> 2 CTAs/SM.  exp via packed f16x2 ex2 (halves MUFU pressure).
__global__ void __launch_bounds__(256, 2) attn_mma(
    const __half* __restrict__ QH, const __half* __restrict__ KH,
    const __half* __restrict__ VH, __half* __restrict__ CH)
{
    extern __shared__ __align__(1024) char sm[];
    const uint32_t sb = smem_u32(sm);
    const int tid = threadIdx.x, wid = tid >> 5, lane = tid & 31;
    const int bh = blockIdx.x, q0 = blockIdx.y * 128;
    const size_t baseQ = (size_t)bh * S_ * HD_ + (size_t)q0 * HD_;
    const size_t baseK = (size_t)bh * S_ * HD_;

    auto issueKV = [&](int ts) {
        const uint32_t st = sb + 16384u + (uint32_t)(ts & 1) * 32768u;
#pragma unroll
        for (int i = 0; i < 4; i++) {
            int fidx = tid + i * 256;            // 0..1023 -> 128 rows x 8 col-chunks
            int r = fidx >> 3, cc = fidx & 7;
            uint32_t off = swz128((uint32_t)(r * 128 + cc * 16));
            const size_t src = baseK + (size_t)(ts * 128 + r) * 64 + cc * 8;
            cpa16(st + off,          KH + src);
            cpa16(st + 16384u + off, VH + src);
        }
        CP_COMMIT();
    };

#pragma unroll
    for (int i = 0; i < 4; i++) {
        int fidx = tid + i * 256;
        int row = fidx >> 3, cc = fidx & 7;
        uint32_t off = swz128((uint32_t)(row * 128 + cc * 16));
        cpa16(sb + off, QH + baseQ + (size_t)row * 64 + cc * 8);
    }
    CP_COMMIT();
    issueKV(0);
    CP_WAIT(1);
    __syncthreads();

    uint32_t qh[4][4];
    {
        const int row16 = (lane & 7) | (((lane >> 3) & 1) << 3);
#pragma unroll
        for (int ds = 0; ds < 4; ds++) {
            const int colb = ((lane >> 4) << 4) + ds * 32;
            uint32_t off = swz128((uint32_t)(((wid * 16 + row16) << 7) + colb));
            ldsm4(qh[ds], sb + off);
        }
    }

    float accO[8][4];
#pragma unroll
    for (int i = 0; i < 8; i++)
#pragma unroll
        for (int j = 0; j < 4; j++) accO[i][j] = 0.0f;
    float accRS[4] = {0.f, 0.f, 0.f, 0.f};       // rowsum via P @ ones
    const uint32_t ones[2] = {0x3C003C00u, 0x3C003C00u};

    const int rowB = (lane & 7) | ((lane >> 4) << 3);
    const int colBh = ((lane >> 3) & 1) << 4;
    const int rowV = lane & 15;
    const int colV = (lane >> 4) * 16;

    for (int ts = 0; ts < 16; ts++) {
        if (ts + 1 < 16) { issueKV(ts + 1); CP_WAIT(1); }
        else             { CP_WAIT(0); }
        __syncthreads();
        const uint32_t st = sb + 16384u + (uint32_t)(ts & 1) * 32768u;

#pragma unroll
        for (int kb = 0; kb < 2; kb++) {
            const int kvo = kb * 64;             // row offset within the 128-row stage

            // S = Qh * Kh  (scale*log2e pre-folded into Q)
            float accS[8][4];
#pragma unroll
            for (int i = 0; i < 8; i++)
#pragma unroll
                for (int j = 0; j < 4; j++) accS[i][j] = 0.0f;

#pragma unroll
            for (int ds = 0; ds < 4; ds++) {
                const int colb = colBh + ds * 32;
#pragma unroll
                for (int p = 0; p < 4; p++) {
                    uint32_t bh_[4];
                    uint32_t off = swz128((uint32_t)(((kvo + p * 16 + rowB) << 7) + colb));
                    ldsm4(bh_, st + off);
#pragma unroll
                    for (int half = 0; half < 2; half++)
                        mma_f16(accS[p * 2 + half], qh[ds], &bh_[half * 2]);
                }
            }

            // P = 2^S : cvt pair -> packed half2, then one f16x2 ex2 per pair
            uint32_t pk[8][2];
#pragma unroll
            for (int nt = 0; nt < 8; nt++) {
                pk[nt][0] = h2ex2(pack2h(accS[nt][0], accS[nt][1]));
                pk[nt][1] = h2ex2(pack2h(accS[nt][2], accS[nt][3]));
            }

            // O += P * Vh ; rowsum += P * ones
#pragma unroll
            for (int p = 0; p < 4; p++) {
                uint32_t ah[4];
                ah[0] = pk[2*p][0];   ah[1] = pk[2*p][1];
                ah[2] = pk[2*p+1][0]; ah[3] = pk[2*p+1][1];
                mma_f16(accRS, ah, ones);
#pragma unroll
                for (int jj = 0; jj < 4; jj++) {
                    uint32_t vh_[4];
                    uint32_t off = swz128((uint32_t)(((kvo + p * 16 + rowV) << 7) + jj * 32 + colV));
                    ldsm4t(vh_, st + 16384u + off);
#pragma unroll
                    for (int half = 0; half < 2; half++)
                        mma_f16(accO[jj * 2 + half], ah, &vh_[half * 2]);
                }
            }
        }
        __syncthreads();
    }

    // accRS[0] = rowsum(row lane>>2), accRS[2] = rowsum(row lane>>2 + 8)
    const float inv0 = 1.0f / (1.0f + accRS[0]);
    const float inv1 = 1.0f / (1.0f + accRS[2]);

    const int b = bh >> 4, h = bh & 15;
    const int qA = q0 + wid * 16 + (lane >> 2);
#pragma unroll
    for (int half = 0; half < 2; half++) {
        const int q = qA + half * 8;
        const float inv = half ? inv1 : inv0;
        const size_t rowb = ((size_t)b * S_ + q) * D_ + h * HD_;
#pragma unroll
        for (int nt = 0; nt < 8; nt++) {
            const int col = nt * 8 + (lane & 3) * 2;
            *(uint32_t*)&CH[rowb + col] =
                pack2h(accO[nt][half * 2] * inv, accO[nt][half * 2 + 1] * inv);
        }
    }
}

// ---------------- host ----------------
extern "C" void kernel_launch(void* const* d_in, const int* in_sizes, int n_in,
                              void* d_out, int out_size)
{
    (void)in_sizes; (void)n_in; (void)out_size;
    const float* query = (const float*)d_in[0];
    const float* key   = (const float*)d_in[1];
    const float* value = (const float*)d_in[2];
    const float* Wq = (const float*)d_in[3];
    const float* bq = (const float*)d_in[4];
    const float* Wk = (const float*)d_in[5];
    const float* bk = (const float*)d_in[6];
    const float* Wv = (const float*)d_in[7];
    const float* bv = (const float*)d_in[8];
    const float* Wf = (const float*)d_in[9];
    const float* bf = (const float*)d_in[10];

    __half* G;
    cudaGetSymbolAddress((void**)&G, g_hf);

    const int n4 = (int)(SZX / 4);
    cvt3_h<<<dim3(n4 / 256, 3), 256>>>(query, key, value, G, n4);
    transpose4_h<<<dim3(32, 32, 4), 256>>>(Wq, Wk, Wv, Wf, G);

    const int gsm = 65536;
    cudaFuncSetAttribute(proj_mma,  cudaFuncAttributeMaxDynamicSharedMemorySize, gsm);
    cudaFuncSetAttribute(final_mma, cudaFuncAttributeMaxDynamicSharedMemorySize, gsm);

    proj_mma<<<dim3(D_ / 128, M_ / 128, 3), 256, gsm>>>(G, bq, bk, bv);

    const int asm_ = 16384 + 2 * 32768;  // 81920
    cudaFuncSetAttribute(attn_mma, cudaFuncAttributeMaxDynamicSharedMemorySize, asm_);
    attn_mma<<<dim3(BH_, S_ / 128), 256, asm_>>>(
        G + O_QH, G + O_KH, G + O_VH, G + O_CH);

    final_mma<<<dim3(OUT_ / 128, M_ / 128), 256, gsm>>>(
        G + O_CH, G + O_WF, bf, (float*)d_out);
}